// round 14
// baseline (speedup 1.0000x reference)
#include <cuda_runtime.h>
#include <cuda_bf16.h>
#include <math.h>

// Problem constants
#define NN   50000
#define EE   800000
#define HID  128
#define SC   128
#define EIN  16
#define TT   5
#define NH   4
#define INVAR 100
#define XDIM 484
#define EPB  32         // edges per CTA
#define NPB  32         // nodes per CTA
#define QS   132        // quad stride in floats (32 rows * 4 + 4 pad)
#define WM1K 488        // padded Wm1 K (228 invar/ef + 4 zero + 256 h)

typedef unsigned long long ull;

// Accumulators (device globals: no allocation allowed)
__device__ float g_msg[(size_t)NN * HID];
__device__ float g_zacc[(size_t)NN * 48];
__device__ float g_cnt[NN];

// K-pair-packed weights: P[(k2*ncol + j)*2 + p] = W[row(2*k2+p)][j]
__device__ __align__(16) float pWe [EIN  * HID];
__device__ __align__(16) float pWm1[WM1K * HID];   // [invar|ef|4 zero rows|h_i|h_j]
__device__ __align__(16) float pWm2[HID  * HID];
__device__ __align__(16) float pWv1[HID  * HID];
__device__ __align__(16) float pWv2[HID  * 80];
__device__ __align__(16) float pWs1[(SC+HID) * HID];
__device__ __align__(16) float pWs2[HID  * HID];

__device__ __forceinline__ float silu_f(float x) {
    return x / (1.0f + __expf(-x));
}

__device__ __forceinline__ void red4(float* p, float x, float y, float z, float w) {
    asm volatile("red.global.add.v4.f32 [%0], {%1,%2,%3,%4};"
                 :: "l"(p), "f"(x), "f"(y), "f"(z), "f"(w) : "memory");
}

__device__ __forceinline__ void ffma2(ull& d, ull a, ull b) {
    asm("fma.rn.f32x2 %0, %1, %2, %0;" : "+l"(d) : "l"(a), "l"(b));
}

__device__ __forceinline__ void addf2(ull& d, ull o) {
    asm("add.rn.f32x2 %0, %0, %1;" : "+l"(d) : "l"(o));
}

__device__ __forceinline__ float psum(ull v) {
    return __uint_as_float((unsigned)v) + __uint_as_float((unsigned)(v >> 32));
}

#define ACC_CLEAR(acc) do { _Pragma("unroll") \
    for (int _i = 0; _i < 4; _i++) { _Pragma("unroll") \
        for (int _j = 0; _j < 4; _j++) (acc)[_i][_j] = 0ULL; } } while (0)

// ---------------------------------------------------------------------------
// k-split GEMM core (edge kernel, 16 warps): warp w owns cols [8w, 8w+8).
// lane = r4(8) x c(2) x s(2):  s = lane&1, c = (lane>>1)&1, r4 = lane>>2.
// Lane covers rows {r4+8i}, cols j0 = 8w+4c..+3, k4 steps {2k8+s}.
// A quad-packed: Ap[k4*QS + row*4 + q]. LDS.128 per (i,k8): 16 distinct
// addresses (256B = 2 cyc) -- no duplicated bytes across c.
// K4 must be even (2*K8). Outputs are s-partial; epi_s combines via shfl.
// ---------------------------------------------------------------------------
__device__ __forceinline__ void gemm_s(
    ull (&acc)[4][4], const float* Ap, int K8,
    const float* __restrict__ P, int ncol, int j0, int r4, int s)
{
    #pragma unroll 2
    for (int k8 = 0; k8 < K8; k8++) {
        const int k4 = 2 * k8 + s;
        const float* pp0 = P + ((size_t)(2 * k4) * ncol + j0) * 2;
        const float* pp1 = pp0 + (size_t)ncol * 2;
        ulonglong2 wa0 = __ldg((const ulonglong2*)pp0);        // k2=2k4, cols j0,j0+1
        ulonglong2 wb0 = __ldg((const ulonglong2*)(pp0 + 4));  // k2=2k4, cols j0+2,j0+3
        ulonglong2 wa1 = __ldg((const ulonglong2*)pp1);        // k2=2k4+1
        ulonglong2 wb1 = __ldg((const ulonglong2*)(pp1 + 4));
        const float* ab = Ap + k4 * QS + r4 * 4;
        #pragma unroll
        for (int i = 0; i < 4; i++) {
            ulonglong2 a = *(const ulonglong2*)(ab + 32 * i);  // row r4+8i, dims 4k4..4k4+3
            ffma2(acc[i][0], a.x, wa0.x);
            ffma2(acc[i][1], a.x, wa0.y);
            ffma2(acc[i][2], a.x, wb0.x);
            ffma2(acc[i][3], a.x, wb0.y);
            ffma2(acc[i][0], a.y, wa1.x);
            ffma2(acc[i][1], a.y, wa1.y);
            ffma2(acc[i][2], a.y, wb1.x);
            ffma2(acc[i][3], a.y, wb1.y);
        }
    }
}

// Epilogue: combine s-partials (shfl xor 1), bias+act, write quad-packed smem.
// s=0 lane writes rows r4, r4+8 ; s=1 lane writes rows r4+16, r4+24.
template<bool ACT>
__device__ __forceinline__ void epi_s(
    ull (&acc)[4][4], const float* __restrict__ bias,
    float* outSp, int j0, int r4, int s)
{
    #pragma unroll
    for (int i = 0; i < 4; i++)
        #pragma unroll
        for (int j = 0; j < 4; j++) {
            ull o = __shfl_xor_sync(0xffffffffu, acc[i][j], 1);
            addf2(acc[i][j], o);
        }
    float4 bv = __ldg((const float4*)(bias + j0));
    float* base = outSp + (j0 >> 2) * QS;
    #pragma unroll
    for (int u = 0; u < 2; u++) {
        int i = s * 2 + u;
        int r = r4 + 8 * i;
        float o0 = psum(acc[i][0]) + bv.x;
        float o1 = psum(acc[i][1]) + bv.y;
        float o2 = psum(acc[i][2]) + bv.z;
        float o3 = psum(acc[i][3]) + bv.w;
        if (ACT) { o0 = silu_f(o0); o1 = silu_f(o1); o2 = silu_f(o2); o3 = silu_f(o3); }
        float4 v; v.x = o0; v.y = o1; v.z = o2; v.w = o3;
        *(float4*)(base + r * 4) = v;
    }
}

// ---------------------------------------------------------------------------
// Node-kernel GEMM (256 threads, 8 warps, unchanged from R12)
// ---------------------------------------------------------------------------
__device__ __forceinline__ void gemm_acc(
    ull (&acc)[4][4], const float* Ap, int K4,
    const float* __restrict__ P, int ncol, int j0, int r4)
{
    #pragma unroll 2
    for (int k4 = 0; k4 < K4; k4++) {
        const float* pp0 = P + ((size_t)(2 * k4) * ncol + j0) * 2;
        const float* pp1 = pp0 + (size_t)ncol * 2;
        ulonglong2 wa0 = __ldg((const ulonglong2*)pp0);
        ulonglong2 wb0 = __ldg((const ulonglong2*)(pp0 + 4));
        ulonglong2 wa1 = __ldg((const ulonglong2*)pp1);
        ulonglong2 wb1 = __ldg((const ulonglong2*)(pp1 + 4));
        const float* ab = Ap + k4 * QS + r4 * 4;
        #pragma unroll
        for (int i = 0; i < 4; i++) {
            ulonglong2 a = *(const ulonglong2*)(ab + 32 * i);
            ffma2(acc[i][0], a.x, wa0.x);
            ffma2(acc[i][1], a.x, wa0.y);
            ffma2(acc[i][2], a.x, wb0.x);
            ffma2(acc[i][3], a.x, wb0.y);
            ffma2(acc[i][0], a.y, wa1.x);
            ffma2(acc[i][1], a.y, wa1.y);
            ffma2(acc[i][2], a.y, wb1.x);
            ffma2(acc[i][3], a.y, wb1.y);
        }
    }
}

template<bool ACT>
__device__ __forceinline__ void epi_smem(
    ull (&acc)[4][4], const float* __restrict__ bias,
    float* outSp, int j0, int r4)
{
    float4 bv = __ldg((const float4*)(bias + j0));
    float* base = outSp + (j0 >> 2) * QS;
    #pragma unroll
    for (int i = 0; i < 4; i++) {
        int r = r4 + 8 * i;
        float o0 = psum(acc[i][0]) + bv.x;
        float o1 = psum(acc[i][1]) + bv.y;
        float o2 = psum(acc[i][2]) + bv.z;
        float o3 = psum(acc[i][3]) + bv.w;
        if (ACT) { o0 = silu_f(o0); o1 = silu_f(o1); o2 = silu_f(o2); o3 = silu_f(o3); }
        float4 v; v.x = o0; v.y = o1; v.z = o2; v.w = o3;
        *(float4*)(base + r * 4) = v;
    }
}

__device__ __forceinline__ void epi_gmem(
    ull (&acc)[4][4], const float* __restrict__ bias,
    float* outG, int rowbase, int rowmax, int j0, int r4)
{
    float4 bv = __ldg((const float4*)(bias + j0));
    #pragma unroll
    for (int i = 0; i < 4; i++) {
        int row = rowbase + r4 + 8 * i;
        if (row < rowmax) {
            float4 v;
            v.x = psum(acc[i][0]) + bv.x;
            v.y = psum(acc[i][1]) + bv.y;
            v.z = psum(acc[i][2]) + bv.z;
            v.w = psum(acc[i][3]) + bv.w;
            *(float4*)(outG + (size_t)row * 128 + j0) = v;
        }
    }
}

// ---------------------------------------------------------------------------
// Prep: zero accumulators + repack weights
// ---------------------------------------------------------------------------
__device__ __forceinline__ void repack_one(const float* __restrict__ W, float* __restrict__ P,
                                           int Kdim, int ncol, size_t idx, size_t stride) {
    size_t tot = (size_t)Kdim * ncol;
    for (size_t i = idx; i < tot; i += stride) {
        size_t p  = i & 1;
        size_t kj = i >> 1;
        size_t k2 = kj / ncol;
        size_t j  = kj % ncol;
        P[i] = W[(2 * k2 + p) * ncol + j];
    }
}

__global__ void prep_kernel(const float* __restrict__ We,  const float* __restrict__ Wm1,
                            const float* __restrict__ Wm2, const float* __restrict__ Wv1,
                            const float* __restrict__ Wv2, const float* __restrict__ Ws1,
                            const float* __restrict__ Ws2) {
    size_t idx = (size_t)blockIdx.x * blockDim.x + threadIdx.x;
    size_t stride = (size_t)gridDim.x * blockDim.x;
    for (size_t i = idx; i < (size_t)NN * HID; i += stride) g_msg[i] = 0.0f;
    for (size_t i = idx; i < (size_t)NN * 48; i += stride) g_zacc[i] = 0.0f;
    for (size_t i = idx; i < NN; i += stride) g_cnt[i] = 0.0f;
    repack_one(We,  pWe,  EIN,      HID, idx, stride);
    repack_one(Wm2, pWm2, HID,      HID, idx, stride);
    repack_one(Wv1, pWv1, HID,      HID, idx, stride);
    repack_one(Wv2, pWv2, HID,      80,  idx, stride);
    repack_one(Ws1, pWs1, SC + HID, HID, idx, stride);
    repack_one(Ws2, pWs2, HID,      HID, idx, stride);
    // pWm1: padded + row-permuted [invar(100)|ef(128)|4 zero rows|h_i|h_j]
    for (size_t i = idx; i < (size_t)WM1K * HID; i += stride) {
        size_t p  = i & 1;
        size_t kj = i >> 1;
        size_t k2 = kj / HID;
        size_t j  = kj % HID;
        size_t k  = 2 * k2 + p;
        float v;
        if (k < 228)      v = Wm1[(k + 256) * HID + j];
        else if (k < 232) v = 0.0f;
        else              v = Wm1[(k - 232) * HID + j];
        pWm1[i] = v;
    }
}

// ncu alignment shims (so -s 5 lands on edge_kernel)
__global__ void dummy_kernel() {}

// ---------------------------------------------------------------------------
// Edge kernel: 32 edges per 512-thread CTA (16 warps, 2 CTAs/SM).
// stage phase A: quads 0..24 invar, 25..56 ef, 57..60 edf staging
//   (k4=57 pairs with zero weight rows 228..231 -> exact zero contribution).
// stage phase B: quads 0..31 h_i, 32..63 h_j.
// After gemm1: msg -> stage 32..63 ; basis -> stage 0..19.
// ---------------------------------------------------------------------------
__global__ void __launch_bounds__(512, 2) edge_kernel(
    const float* __restrict__ Z, const float* __restrict__ h,
    const int* __restrict__ ei,
    const float* __restrict__ edf, const float* __restrict__ edv,
    const float* __restrict__ be,  const float* __restrict__ bm1,
    const float* __restrict__ bm2, const float* __restrict__ bv1,
    const float* __restrict__ bv2)
{
    extern __shared__ float sm[];
    float* stage = sm;                      // 64*QS = 8448
    float* h1p   = sm + 64 * QS;            // 32*QS = 4224
    float* zs    = h1p + 32 * QS;           // 1920 (stride 60: d*20+t*4+h)
    int*   ssrc  = (int*)(zs + 32 * 60);    // 32
    int*   sdst  = ssrc + 32;               // 32
    float* edfp  = stage + 57 * QS;         // quads 57..60

    const int tid  = threadIdx.x;
    const int warp = tid >> 5;
    const int lane = tid & 31;
    const int s    = lane & 1;
    const int r4   = lane >> 2;
    const int j0   = warp * 8 + ((lane >> 1) & 1) * 4;
    const int e0   = blockIdx.x * EPB;

    // ---- stage indices, edf (quad-packed into stage quads 57..60), Z_ij ----
    if (tid < EPB) {
        ssrc[tid] = ei[e0 + tid];
        sdst[tid] = ei[EE + e0 + tid];
    }
    for (int i = tid; i < EPB * EIN; i += 512) {
        int e = i >> 4, k = i & 15;
        edfp[(k >> 2) * QS + e * 4 + (k & 3)] = edf[(size_t)(e0 + e) * EIN + k];
    }
    __syncthreads();

    // Z_ij, t < 4: Z[dst] - Z[src]
    for (int i = tid; i < EPB * 48; i += 512) {
        int e = i / 48, r = i % 48;
        int d = r >> 4, q = r & 15;
        float v = __ldg(Z + (size_t)sdst[e] * 48 + r) - __ldg(Z + (size_t)ssrc[e] * 48 + r);
        zs[e * 60 + d * 20 + q] = v;
    }
    // Z_ij, t == 4: edge_distance_vec broadcast over heads
    for (int i = tid; i < EPB * 12; i += 512) {
        int e = i / 12, r = i % 12;
        int d = r >> 2, hh = r & 3;
        zs[e * 60 + d * 20 + 16 + hh] = __ldg(edv + (size_t)(e0 + e) * 3 + d);
    }
    __syncthreads();

    // ---- invariants + L2 normalize -> x dims 0..99 (quads 0..24) ----
    for (int eloc = 0; eloc < 2; eloc++) {
        int e = warp * 2 + eloc;
        float v[4];
        float sq = 0.0f;
        #pragma unroll
        for (int u = 0; u < 4; u++) {
            int m = lane + u * 32;
            float val = 0.0f;
            if (m < INVAR) {
                int t = m / 20, rem = m % 20;
                int rr = rem >> 2, hh = rem & 3;
                const float* z = zs + e * 60;
                val = z[0 * 20 + t * 4 + hh] * z[0 * 20 + rr * 4 + hh]
                    + z[1 * 20 + t * 4 + hh] * z[1 * 20 + rr * 4 + hh]
                    + z[2 * 20 + t * 4 + hh] * z[2 * 20 + rr * 4 + hh];
            }
            v[u] = val;
            sq += val * val;
        }
        #pragma unroll
        for (int off = 16; off > 0; off >>= 1)
            sq += __shfl_xor_sync(0xffffffffu, sq, off);
        float inv = 1.0f / fmaxf(sqrtf(sq), 1e-12f);
        #pragma unroll
        for (int u = 0; u < 4; u++) {
            int m = lane + u * 32;
            if (m < INVAR)
                stage[(m >> 2) * QS + e * 4 + (m & 3)] = v[u] * inv;
        }
    }

    // ---- edge_feature = edf @ We + be -> x dims 100..227 (quads 25..56) ----
    {
        ull acc[4][4]; ACC_CLEAR(acc);
        gemm_s(acc, edfp, EIN / 8, pWe, HID, j0, r4, s);
        epi_s<false>(acc, be, stage + 25 * QS, j0, r4, s);
    }
    __syncthreads();

    // ---- gemm1 phase A over [invar|ef|edf-pad] (k4 0..57 = 29 k8) ----
    ull acc1[4][4]; ACC_CLEAR(acc1);
    gemm_s(acc1, stage, 29, pWm1, HID, j0, r4, s);
    __syncthreads();

    // ---- refill stage: h_i -> quads 0..31, h_j -> quads 32..63 ----
    for (int i = tid; i < EPB * 32; i += 512) {
        int e = i >> 5, c = i & 31;
        float4 vi = __ldg((const float4*)(h + (size_t)sdst[e] * 128 + c * 4));
        float4 vj = __ldg((const float4*)(h + (size_t)ssrc[e] * 128 + c * 4));
        *(float4*)(stage + c * QS + e * 4) = vi;
        *(float4*)(stage + (32 + c) * QS + e * 4) = vj;
    }
    __syncthreads();

    // ---- gemm1 phase B over [h_i|h_j] (weight rows 232..487) + epilogue ----
    gemm_s(acc1, stage, 32, pWm1 + (size_t)232 * HID, HID, j0, r4, s);
    epi_s<true>(acc1, bm1, h1p, j0, r4, s);
    __syncthreads();

    // ---- gemm2: msg = silu(h1 @ Wm2 + bm2) -> stage quads 32..63 ----
    {
        ull acc[4][4]; ACC_CLEAR(acc);
        gemm_s(acc, h1p, HID / 8, pWm2, HID, j0, r4, s);
        epi_s<true>(acc, bm2, stage + 32 * QS, j0, r4, s);
    }
    __syncthreads();

    // ---- gemm3: vh = silu(msg @ Wv1 + bv1) -> h1p ----
    {
        ull acc[4][4]; ACC_CLEAR(acc);
        gemm_s(acc, stage + 32 * QS, HID / 8, pWv1, HID, j0, r4, s);
        epi_s<true>(acc, bv1, h1p, j0, r4, s);
    }
    __syncthreads();

    // ---- basis = vh @ Wv2 + bv2 (80 cols, warps 0..9) -> stage quads 0..19 ----
    if (warp < 10) {
        ull acc[4][4]; ACC_CLEAR(acc);
        gemm_s(acc, h1p, HID / 8, pWv2, 80, j0, r4, s);
        epi_s<false>(acc, bv2, stage, j0, r4, s);
    }
    __syncthreads();

    // ---- scatter-reduce ----
    // msg sum (stage quads 32..63)
    for (int i = tid; i < EPB * 32; i += 512) {
        int e = i >> 5, c = i & 31;
        float4 v = *(const float4*)(stage + (32 + c) * QS + e * 4);
        red4(g_msg + (size_t)sdst[e] * 128 + c * 4, v.x, v.y, v.z, v.w);
    }
    if (tid < EPB) atomicAdd(&g_cnt[sdst[tid]], 1.0f);
    // Z_agg[e][d][k][h] = sum_t Zij[d][t][h] * basis[t][k][h]
    for (int i = tid; i < EPB * 12; i += 512) {
        int e = i / 12, rr = i % 12;
        int d = rr >> 2, kk = rr & 3;
        const float* z = zs + e * 60 + d * 20;   // z[t*4 + h]
        float o[4];
        #pragma unroll
        for (int hh = 0; hh < 4; hh++) {
            float sacc = 0.0f;
            #pragma unroll
            for (int t = 0; t < TT; t++) {
                int k = t * 16 + kk * 4 + hh;    // basis dim
                sacc += z[t * 4 + hh] * stage[(k >> 2) * QS + e * 4 + (k & 3)];
            }
            o[hh] = sacc;
        }
        red4(g_zacc + (size_t)sdst[e] * 48 + rr * 4, o[0], o[1], o[2], o[3]);
    }
}

// ---------------------------------------------------------------------------
// Node kernel: 32 nodes per 256-thread CTA (unchanged)
// out layout: [ Z_out : NN*48 ][ h_out : NN*128 ]
// ---------------------------------------------------------------------------
__global__ void __launch_bounds__(256, 3) node_kernel(
    const float* __restrict__ h,
    const float* __restrict__ bs1, const float* __restrict__ bs2,
    float* __restrict__ out)
{
    extern __shared__ float sm[];
    float* xnp = sm;                  // 64 quads = 8448
    float* t1p = sm + 64 * QS;        // 32 quads = 4224

    const int tid  = threadIdx.x;
    const int warp = tid >> 5;
    const int lane = tid & 31;
    const int r4   = lane >> 2;
    const int j0   = warp * 16 + (lane & 3) * 4;
    const int n0   = blockIdx.x * NPB;

    for (int i = tid; i < NPB * 64; i += 256) {
        int v = i >> 6, c = i & 63;
        int n = n0 + v;
        int nc = n < NN ? n : (NN - 1);
        float4 val;
        if (c < 32) val = __ldg((const float4*)(h + (size_t)nc * 128 + c * 4));
        else        val = *(const float4*)(g_msg + (size_t)nc * 128 + (c - 32) * 4);
        *(float4*)(xnp + c * QS + v * 4) = val;
    }
    __syncthreads();

    {
        ull acc[4][4]; ACC_CLEAR(acc);
        gemm_acc(acc, xnp, (SC + HID) / 4, pWs1, HID, j0, r4);
        epi_smem<true>(acc, bs1, t1p, j0, r4);
    }
    __syncthreads();
    {
        ull acc[4][4]; ACC_CLEAR(acc);
        gemm_acc(acc, t1p, HID / 4, pWs2, HID, j0, r4);
        epi_gmem(acc, bs2, out + (size_t)NN * 48, n0, NN, j0, r4);
    }

    for (int i = tid; i < NPB * 48; i += 256) {
        int v = i / 48, r = i % 48;
        int n = n0 + v;
        if (n < NN) {
            float c = fmaxf(g_cnt[n], 1.0f);
            out[(size_t)n * 48 + r] = g_zacc[(size_t)n * 48 + r] * (1.0f / c);
        }
    }
}

// ---------------------------------------------------------------------------
extern "C" void kernel_launch(void* const* d_in, const int* in_sizes, int n_in,
                              void* d_out, int out_size) {
    const float* Z   = (const float*)d_in[0];
    const float* h   = (const float*)d_in[1];
    const int*   ei  = (const int*)d_in[2];
    const float* edf = (const float*)d_in[3];
    const float* edv = (const float*)d_in[4];
    // d_in[5] = edge_distance (unused by the reference)
    const float* We  = (const float*)d_in[6];
    const float* be  = (const float*)d_in[7];
    const float* Wm1 = (const float*)d_in[8];
    const float* bm1 = (const float*)d_in[9];
    const float* Wm2 = (const float*)d_in[10];
    const float* bm2 = (const float*)d_in[11];
    const float* Wv1 = (const float*)d_in[12];
    const float* bv1 = (const float*)d_in[13];
    const float* Wv2 = (const float*)d_in[14];
    const float* bv2 = (const float*)d_in[15];
    const float* Ws1 = (const float*)d_in[16];
    const float* bs1 = (const float*)d_in[17];
    const float* Ws2 = (const float*)d_in[18];
    const float* bs2 = (const float*)d_in[19];
    float* out = (float*)d_out;

    const int edge_floats = 64 * QS + 32 * QS + 32 * 60 + 64;
    const int edge_smem = edge_floats * 4;             // 58,624 B -> 2 CTAs/SM @512thr
    const int node_smem = (64 * QS + 32 * QS) * 4;     // 50,688 B
    cudaFuncSetAttribute(edge_kernel, cudaFuncAttributeMaxDynamicSharedMemorySize, edge_smem);
    cudaFuncSetAttribute(node_kernel, cudaFuncAttributeMaxDynamicSharedMemorySize, node_smem);

    prep_kernel<<<1024, 256>>>(We, Wm1, Wm2, Wv1, Wv2, Ws1, Ws2);
    dummy_kernel<<<1, 32>>>();
    dummy_kernel<<<1, 32>>>();
    edge_kernel<<<EE / EPB, 512, edge_smem>>>(Z, h, ei, edf, edv,
                                              be, bm1, bm2, bv1, bv2);
    node_kernel<<<(NN + NPB - 1) / NPB, 256, node_smem>>>(h, bs1, bs2, out);
}

// round 16
// speedup vs baseline: 1.9833x; 1.9833x over previous
#include <cuda_runtime.h>
#include <cuda_bf16.h>
#include <math.h>

// Problem constants
#define NN   50000
#define EE   800000
#define HID  128
#define SC   128
#define EIN  16
#define TT   5
#define NH   4
#define INVAR 100
#define XDIM 484
#define EPB  32         // edges per CTA
#define NPB  32         // nodes per CTA
#define QS   132        // quad stride in floats (32 rows * 4 + 4 pad)
#define WPAD 320        // weight tail pad (prefetch overread safety)

typedef unsigned long long ull;

// Accumulators (device globals: no allocation allowed)
__device__ float g_msg[(size_t)NN * HID];
__device__ float g_zacc[(size_t)NN * 48];
__device__ float g_cnt[NN];

// K-pair-packed weights: P[(k2*ncol + j)*2 + p] = W[row(2*k2+p)][j]
__device__ __align__(16) float pWe [EIN  * HID + WPAD];
__device__ __align__(16) float pWm1[XDIM * HID + WPAD];   // row-permuted: [invar|ef|h_i|h_j]
__device__ __align__(16) float pWm2[HID  * HID + WPAD];
__device__ __align__(16) float pWv1[HID  * HID + WPAD];
__device__ __align__(16) float pWv2[HID  * 80  + WPAD];
__device__ __align__(16) float pWs1[(SC+HID) * HID + WPAD];
__device__ __align__(16) float pWs2[HID  * HID + WPAD];

__device__ __forceinline__ float silu_f(float x) {
    return x / (1.0f + __expf(-x));
}

__device__ __forceinline__ void red4(float* p, float x, float y, float z, float w) {
    asm volatile("red.global.add.v4.f32 [%0], {%1,%2,%3,%4};"
                 :: "l"(p), "f"(x), "f"(y), "f"(z), "f"(w) : "memory");
}

__device__ __forceinline__ void ffma2(ull& d, ull a, ull b) {
    asm("fma.rn.f32x2 %0, %1, %2, %0;" : "+l"(d) : "l"(a), "l"(b));
}

__device__ __forceinline__ float psum(ull v) {
    return __uint_as_float((unsigned)v) + __uint_as_float((unsigned)(v >> 32));
}

#define ACC_CLEAR(acc) do { _Pragma("unroll") \
    for (int _i = 0; _i < 4; _i++) { _Pragma("unroll") \
        for (int _j = 0; _j < 4; _j++) (acc)[_i][_j] = 0ULL; } } while (0)

// ---------------------------------------------------------------------------
// K-loop core (quad A layout) with software-pipelined weight prefetch.
// A quad-packed in shared: Aq[k4*QS + row*4 + q] = A[row][4*k4+q].
// Warp w owns cols [16w,16w+16); r4 = lane>>2 -> rows {r4+8i}; c = lane&3 ->
// cols j0 = 16w+4c..+3. Weight loads non-redundant across warps.
// Iteration k4 prefetches weights for k4+1 (over-reads <= WPAD at the end).
// ---------------------------------------------------------------------------
__device__ __forceinline__ void gemm_acc(
    ull (&acc)[4][4], const float* Ap, int K4,
    const float* __restrict__ P, int ncol, int j0, int r4)
{
    const float* pw = P + (size_t)j0 * 2;
    const int step = 4 * ncol;
    ulonglong2 wa0 = __ldg((const ulonglong2*)pw);
    ulonglong2 wb0 = __ldg((const ulonglong2*)(pw + 4));
    ulonglong2 wa1 = __ldg((const ulonglong2*)(pw + 2 * ncol));
    ulonglong2 wb1 = __ldg((const ulonglong2*)(pw + 2 * ncol + 4));
    for (int k4 = 0; k4 < K4; k4++) {
        const float* pn = pw + (size_t)(k4 + 1) * step;
        ulonglong2 na0 = __ldg((const ulonglong2*)pn);
        ulonglong2 nb0 = __ldg((const ulonglong2*)(pn + 4));
        ulonglong2 na1 = __ldg((const ulonglong2*)(pn + 2 * ncol));
        ulonglong2 nb1 = __ldg((const ulonglong2*)(pn + 2 * ncol + 4));
        const float* ab = Ap + k4 * QS + r4 * 4;
        #pragma unroll
        for (int i = 0; i < 4; i++) {
            ulonglong2 a = *(const ulonglong2*)(ab + 32 * i);  // row r4+8i, dims 4k4..4k4+3
            ffma2(acc[i][0], a.x, wa0.x);
            ffma2(acc[i][1], a.x, wa0.y);
            ffma2(acc[i][2], a.x, wb0.x);
            ffma2(acc[i][3], a.x, wb0.y);
            ffma2(acc[i][0], a.y, wa1.x);
            ffma2(acc[i][1], a.y, wa1.y);
            ffma2(acc[i][2], a.y, wb1.x);
            ffma2(acc[i][3], a.y, wb1.y);
        }
        wa0 = na0; wb0 = nb0; wa1 = na1; wb1 = nb1;
    }
}

template<bool ACT>
__device__ __forceinline__ void epi_smem(
    ull (&acc)[4][4], const float* __restrict__ bias,
    float* outSp, int j0, int r4)
{
    float4 bv = __ldg((const float4*)(bias + j0));
    float* base = outSp + (j0 >> 2) * QS;   // output quad = j0/4
    #pragma unroll
    for (int i = 0; i < 4; i++) {
        int r = r4 + 8 * i;
        float o0 = psum(acc[i][0]) + bv.x;
        float o1 = psum(acc[i][1]) + bv.y;
        float o2 = psum(acc[i][2]) + bv.z;
        float o3 = psum(acc[i][3]) + bv.w;
        if (ACT) { o0 = silu_f(o0); o1 = silu_f(o1); o2 = silu_f(o2); o3 = silu_f(o3); }
        float4 v; v.x = o0; v.y = o1; v.z = o2; v.w = o3;
        *(float4*)(base + r * 4) = v;
    }
}

__device__ __forceinline__ void epi_gmem(
    ull (&acc)[4][4], const float* __restrict__ bias,
    float* outG, int rowbase, int rowmax, int j0, int r4)
{
    float4 bv = __ldg((const float4*)(bias + j0));
    #pragma unroll
    for (int i = 0; i < 4; i++) {
        int row = rowbase + r4 + 8 * i;
        if (row < rowmax) {
            float4 v;
            v.x = psum(acc[i][0]) + bv.x;
            v.y = psum(acc[i][1]) + bv.y;
            v.z = psum(acc[i][2]) + bv.z;
            v.w = psum(acc[i][3]) + bv.w;
            *(float4*)(outG + (size_t)row * 128 + j0) = v;
        }
    }
}

// ---------------------------------------------------------------------------
// Prep: zero accumulators + repack weights (Wm1 with row permutation)
// ---------------------------------------------------------------------------
template<bool PERM>
__device__ __forceinline__ void repack_one(const float* __restrict__ W, float* __restrict__ P,
                                           int Kdim, int ncol, size_t idx, size_t stride) {
    size_t tot = (size_t)Kdim * ncol;
    for (size_t i = idx; i < tot; i += stride) {
        size_t p  = i & 1;
        size_t kj = i >> 1;
        size_t k2 = kj / ncol;
        size_t j  = kj % ncol;
        size_t k  = 2 * k2 + p;
        if (PERM) k = (k < 228) ? (k + 256) : (k - 228);   // [invar|ef|h_i|h_j]
        P[i] = W[k * ncol + j];
    }
}

__global__ void prep_kernel(const float* __restrict__ We,  const float* __restrict__ Wm1,
                            const float* __restrict__ Wm2, const float* __restrict__ Wv1,
                            const float* __restrict__ Wv2, const float* __restrict__ Ws1,
                            const float* __restrict__ Ws2) {
    size_t idx = (size_t)blockIdx.x * blockDim.x + threadIdx.x;
    size_t stride = (size_t)gridDim.x * blockDim.x;
    for (size_t i = idx; i < (size_t)NN * HID; i += stride) g_msg[i] = 0.0f;
    for (size_t i = idx; i < (size_t)NN * 48; i += stride) g_zacc[i] = 0.0f;
    for (size_t i = idx; i < NN; i += stride) g_cnt[i] = 0.0f;
    repack_one<false>(We,  pWe,  EIN,      HID, idx, stride);
    repack_one<true >(Wm1, pWm1, XDIM,     HID, idx, stride);
    repack_one<false>(Wm2, pWm2, HID,      HID, idx, stride);
    repack_one<false>(Wv1, pWv1, HID,      HID, idx, stride);
    repack_one<false>(Wv2, pWv2, HID,      80,  idx, stride);
    repack_one<false>(Ws1, pWs1, SC + HID, HID, idx, stride);
    repack_one<false>(Ws2, pWs2, HID,      HID, idx, stride);
}

// ncu alignment shims (so -s 5 lands on edge_kernel)
__global__ void dummy_kernel() {}

// ---------------------------------------------------------------------------
// Edge kernel: 32 edges per 256-thread CTA, 3 CTAs/SM.
// Shared (floats): stage 64 quads (8448) | h1p 32 quads (4224) | zs 1920 | idx
// stage phase A: quads 0..24 invar, 25..56 ef, 57..60 edf input.
// stage phase B: quads 0..31 h_i, 32..63 h_j.
// After gemm1: msg -> stage quads 32..63 ; basis -> stage quads 0..19.
// ---------------------------------------------------------------------------
__global__ void __launch_bounds__(256, 3) edge_kernel(
    const float* __restrict__ Z, const float* __restrict__ h,
    const int* __restrict__ ei,
    const float* __restrict__ edf, const float* __restrict__ edv,
    const float* __restrict__ be,  const float* __restrict__ bm1,
    const float* __restrict__ bm2, const float* __restrict__ bv1,
    const float* __restrict__ bv2)
{
    extern __shared__ float sm[];
    float* stage = sm;                      // 64*QS = 8448
    float* h1p   = sm + 64 * QS;            // 32*QS = 4224
    float* zs    = h1p + 32 * QS;           // 1920 (stride 60: d*20+t*4+h)
    int*   ssrc  = (int*)(zs + 32 * 60);    // 32
    int*   sdst  = ssrc + 32;               // 32
    float* edfp  = stage + 57 * QS;         // quads 57..60

    const int tid  = threadIdx.x;
    const int warp = tid >> 5;
    const int lane = tid & 31;
    const int r4   = lane >> 2;
    const int j0   = warp * 16 + (lane & 3) * 4;
    const int e0   = blockIdx.x * EPB;

    // ---- stage indices, edf (quad-packed into stage quads 57..60), Z_ij ----
    if (tid < EPB) {
        ssrc[tid] = ei[e0 + tid];
        sdst[tid] = ei[EE + e0 + tid];
    }
    for (int i = tid; i < EPB * EIN; i += 256) {
        int e = i >> 4, k = i & 15;
        edfp[(k >> 2) * QS + e * 4 + (k & 3)] = edf[(size_t)(e0 + e) * EIN + k];
    }
    __syncthreads();

    // Z_ij, t < 4: Z[dst] - Z[src]
    for (int i = tid; i < EPB * 48; i += 256) {
        int e = i / 48, r = i % 48;
        int d = r >> 4, q = r & 15;
        float v = __ldg(Z + (size_t)sdst[e] * 48 + r) - __ldg(Z + (size_t)ssrc[e] * 48 + r);
        zs[e * 60 + d * 20 + q] = v;
    }
    // Z_ij, t == 4: edge_distance_vec broadcast over heads
    for (int i = tid; i < EPB * 12; i += 256) {
        int e = i / 12, r = i % 12;
        int d = r >> 2, hh = r & 3;
        zs[e * 60 + d * 20 + 16 + hh] = __ldg(edv + (size_t)(e0 + e) * 3 + d);
    }
    __syncthreads();

    // ---- invariants + L2 normalize -> x dims 0..99 (quads 0..24) ----
    for (int eloc = 0; eloc < 4; eloc++) {
        int e = warp * 4 + eloc;
        float v[4];
        float sq = 0.0f;
        #pragma unroll
        for (int u = 0; u < 4; u++) {
            int m = lane + u * 32;
            float val = 0.0f;
            if (m < INVAR) {
                int t = m / 20, rem = m % 20;
                int rr = rem >> 2, hh = rem & 3;
                const float* z = zs + e * 60;
                val = z[0 * 20 + t * 4 + hh] * z[0 * 20 + rr * 4 + hh]
                    + z[1 * 20 + t * 4 + hh] * z[1 * 20 + rr * 4 + hh]
                    + z[2 * 20 + t * 4 + hh] * z[2 * 20 + rr * 4 + hh];
            }
            v[u] = val;
            sq += val * val;
        }
        #pragma unroll
        for (int off = 16; off > 0; off >>= 1)
            sq += __shfl_xor_sync(0xffffffffu, sq, off);
        float inv = 1.0f / fmaxf(sqrtf(sq), 1e-12f);
        #pragma unroll
        for (int u = 0; u < 4; u++) {
            int m = lane + u * 32;
            if (m < INVAR)
                stage[(m >> 2) * QS + e * 4 + (m & 3)] = v[u] * inv;
        }
    }

    // ---- edge_feature = edf @ We + be -> x dims 100..227 (quads 25..56) ----
    {
        ull acc[4][4]; ACC_CLEAR(acc);
        gemm_acc(acc, edfp, EIN / 4, pWe, HID, j0, r4);
        epi_smem<false>(acc, be, stage + 25 * QS, j0, r4);
    }
    __syncthreads();

    // ---- gemm1 phase A over [invar|ef] (quads 0..56); accs live across sync ----
    ull acc1[4][4]; ACC_CLEAR(acc1);
    gemm_acc(acc1, stage, 57, pWm1, HID, j0, r4);
    __syncthreads();

    // ---- refill stage: h_i -> quads 0..31, h_j -> quads 32..63 ----
    for (int i = tid; i < EPB * 32; i += 256) {
        int e = i >> 5, c = i & 31;
        float4 vi = __ldg((const float4*)(h + (size_t)sdst[e] * 128 + c * 4));
        float4 vj = __ldg((const float4*)(h + (size_t)ssrc[e] * 128 + c * 4));
        *(float4*)(stage + c * QS + e * 4) = vi;
        *(float4*)(stage + (32 + c) * QS + e * 4) = vj;
    }
    __syncthreads();

    // ---- gemm1 phase B over [h_i|h_j] (weight rows 228..483) + epilogue ----
    gemm_acc(acc1, stage, 64, pWm1 + (size_t)228 * HID, HID, j0, r4);
    epi_smem<true>(acc1, bm1, h1p, j0, r4);
    __syncthreads();

    // ---- gemm2: msg = silu(h1 @ Wm2 + bm2) -> stage quads 32..63 ----
    {
        ull acc[4][4]; ACC_CLEAR(acc);
        gemm_acc(acc, h1p, HID / 4, pWm2, HID, j0, r4);
        epi_smem<true>(acc, bm2, stage + 32 * QS, j0, r4);
    }
    __syncthreads();

    // ---- gemm3: vh = silu(msg @ Wv1 + bv1) -> h1p ----
    {
        ull acc[4][4]; ACC_CLEAR(acc);
        gemm_acc(acc, stage + 32 * QS, HID / 4, pWv1, HID, j0, r4);
        epi_smem<true>(acc, bv1, h1p, j0, r4);
    }
    __syncthreads();

    // ---- basis GEMM (warps 0..4) || msg scatter + counts (warps 5..7) ----
    // basis writes stage quads 0..19 ; scatter reads stage quads 32..63.
    if (warp < 5) {
        ull acc[4][4]; ACC_CLEAR(acc);
        gemm_acc(acc, h1p, HID / 4, pWv2, 80, j0, r4);
        epi_smem<false>(acc, bv2, stage, j0, r4);
    } else {
        for (int i = tid - 160; i < EPB * 32; i += 96) {
            int e = i >> 5, c = i & 31;
            float4 v = *(const float4*)(stage + (32 + c) * QS + e * 4);
            red4(g_msg + (size_t)sdst[e] * 128 + c * 4, v.x, v.y, v.z, v.w);
        }
        if (tid >= 160 && tid < 160 + EPB)
            atomicAdd(&g_cnt[sdst[tid - 160]], 1.0f);
    }
    __syncthreads();

    // ---- Z_agg scatter: Z_agg[e][d][k][h] = sum_t Zij[d][t][h]*basis[t][k][h]
    for (int i = tid; i < EPB * 12; i += 256) {
        int e = i / 12, rr = i % 12;
        int d = rr >> 2, kk = rr & 3;
        const float* z = zs + e * 60 + d * 20;   // z[t*4 + h]
        float o[4];
        #pragma unroll
        for (int hh = 0; hh < 4; hh++) {
            float s = 0.0f;
            #pragma unroll
            for (int t = 0; t < TT; t++) {
                int k = t * 16 + kk * 4 + hh;    // basis dim
                s += z[t * 4 + hh] * stage[(k >> 2) * QS + e * 4 + (k & 3)];
            }
            o[hh] = s;
        }
        red4(g_zacc + (size_t)sdst[e] * 48 + rr * 4, o[0], o[1], o[2], o[3]);
    }
}

// ---------------------------------------------------------------------------
// Node kernel: 32 nodes per 256-thread CTA
// out layout: [ Z_out : NN*48 ][ h_out : NN*128 ]
// ---------------------------------------------------------------------------
__global__ void __launch_bounds__(256, 3) node_kernel(
    const float* __restrict__ h,
    const float* __restrict__ bs1, const float* __restrict__ bs2,
    float* __restrict__ out)
{
    extern __shared__ float sm[];
    float* xnp = sm;                  // 64 quads = 8448
    float* t1p = sm + 64 * QS;        // 32 quads = 4224

    const int tid  = threadIdx.x;
    const int warp = tid >> 5;
    const int lane = tid & 31;
    const int r4   = lane >> 2;
    const int j0   = warp * 16 + (lane & 3) * 4;
    const int n0   = blockIdx.x * NPB;

    for (int i = tid; i < NPB * 64; i += 256) {
        int v = i >> 6, c = i & 63;
        int n = n0 + v;
        int nc = n < NN ? n : (NN - 1);
        float4 val;
        if (c < 32) val = __ldg((const float4*)(h + (size_t)nc * 128 + c * 4));
        else        val = *(const float4*)(g_msg + (size_t)nc * 128 + (c - 32) * 4);
        *(float4*)(xnp + c * QS + v * 4) = val;
    }
    __syncthreads();

    {
        ull acc[4][4]; ACC_CLEAR(acc);
        gemm_acc(acc, xnp, (SC + HID) / 4, pWs1, HID, j0, r4);
        epi_smem<true>(acc, bs1, t1p, j0, r4);
    }
    __syncthreads();
    {
        ull acc[4][4]; ACC_CLEAR(acc);
        gemm_acc(acc, t1p, HID / 4, pWs2, HID, j0, r4);
        epi_gmem(acc, bs2, out + (size_t)NN * 48, n0, NN, j0, r4);
    }

    for (int i = tid; i < NPB * 48; i += 256) {
        int v = i / 48, r = i % 48;
        int n = n0 + v;
        if (n < NN) {
            float c = fmaxf(g_cnt[n], 1.0f);
            out[(size_t)n * 48 + r] = g_zacc[(size_t)n * 48 + r] * (1.0f / c);
        }
    }
}

// ---------------------------------------------------------------------------
extern "C" void kernel_launch(void* const* d_in, const int* in_sizes, int n_in,
                              void* d_out, int out_size) {
    const float* Z   = (const float*)d_in[0];
    const float* h   = (const float*)d_in[1];
    const int*   ei  = (const int*)d_in[2];
    const float* edf = (const float*)d_in[3];
    const float* edv = (const float*)d_in[4];
    // d_in[5] = edge_distance (unused by the reference)
    const float* We  = (const float*)d_in[6];
    const float* be  = (const float*)d_in[7];
    const float* Wm1 = (const float*)d_in[8];
    const float* bm1 = (const float*)d_in[9];
    const float* Wm2 = (const float*)d_in[10];
    const float* bm2 = (const float*)d_in[11];
    const float* Wv1 = (const float*)d_in[12];
    const float* bv1 = (const float*)d_in[13];
    const float* Wv2 = (const float*)d_in[14];
    const float* bv2 = (const float*)d_in[15];
    const float* Ws1 = (const float*)d_in[16];
    const float* bs1 = (const float*)d_in[17];
    const float* Ws2 = (const float*)d_in[18];
    const float* bs2 = (const float*)d_in[19];
    float* out = (float*)d_out;

    const int edge_floats = 64 * QS + 32 * QS + 32 * 60 + 64;
    const int edge_smem = edge_floats * 4;             // 58,624 B -> 3 CTAs/SM
    const int node_smem = (64 * QS + 32 * QS) * 4;     // 50,688 B
    cudaFuncSetAttribute(edge_kernel, cudaFuncAttributeMaxDynamicSharedMemorySize, edge_smem);
    cudaFuncSetAttribute(node_kernel, cudaFuncAttributeMaxDynamicSharedMemorySize, node_smem);

    prep_kernel<<<1024, 256>>>(We, Wm1, Wm2, Wv1, Wv2, Ws1, Ws2);
    dummy_kernel<<<1, 32>>>();
    dummy_kernel<<<1, 32>>>();
    edge_kernel<<<EE / EPB, 256, edge_smem>>>(Z, h, ei, edf, edv,
                                              be, bm1, bm2, bv1, bv2);
    node_kernel<<<(NN + NPB - 1) / NPB, 256, node_smem>>>(h, bs1, bs2, out);
}